// round 1
// baseline (speedup 1.0000x reference)
#include <cuda_runtime.h>
#include <cstdint>
#include <math.h>

#define BB 64
#define TT 1024
#define II 512
#define HH 512

#define NCTA 128
#define NTHR 256

// ---------------- device scratch (static allocs are the sanctioned scratch) ---
__device__ float g_z[(size_t)BB * TT * HH];   // sigmoid(x@W + b_w), [(b*T+t)][h]
__device__ float g_y[2][HH * BB];             // recurrent state, [h][b] layout
__device__ unsigned int g_bar_count;
__device__ unsigned int g_bar_gen;

// ---------------- grid barrier (128 co-resident CTAs) ------------------------
__device__ __forceinline__ void grid_barrier(unsigned int nctas) {
    __syncthreads();
    __threadfence();
    if (threadIdx.x == 0) {
        unsigned int gen = *(volatile unsigned int*)&g_bar_gen;
        unsigned int ticket = atomicAdd(&g_bar_count, 1u);
        if (ticket == nctas - 1u) {
            atomicExch(&g_bar_count, 0u);
            __threadfence();
            atomicAdd(&g_bar_gen, 1u);
        } else {
            while (*(volatile unsigned int*)&g_bar_gen == gen) { }
        }
    }
    __syncthreads();
    __threadfence();
}

// ---------------- Phase 1: z = sigmoid(x @ W + b_w) --------------------------
// M = B*T = 65536, K = I = 512, N = H = 512
// BM=BN=128, BK=8, 256 threads, 8x8 register tile per thread.
__global__ __launch_bounds__(256) void zgemm_kernel(
    const float* __restrict__ x, const float* __restrict__ W,
    const float* __restrict__ bw)
{
    __shared__ float As[8][128];   // [k][m]
    __shared__ float Bs[8][128];   // [k][n]

    const int tid = threadIdx.x;
    const int bm = blockIdx.y * 128;
    const int bn = blockIdx.x * 128;

    const int lm = tid >> 1;            // 0..127
    const int lk = (tid & 1) * 4;       // 0 or 4
    const int wk = tid >> 5;            // 0..7
    const int wn = (tid & 31) * 4;      // 0..124

    const int tm = (tid >> 4) * 8;      // 0..120
    const int tn = (tid & 15) * 8;      // 0..120

    float acc[8][8];
#pragma unroll
    for (int i = 0; i < 8; i++)
#pragma unroll
        for (int j = 0; j < 8; j++) acc[i][j] = 0.0f;

    const float* xg = x + (size_t)(bm + lm) * II + lk;
    const float* Wg = W + (size_t)wk * HH + bn + wn;

    for (int k0 = 0; k0 < II; k0 += 8) {
        float4 a4 = *(const float4*)(xg + k0);
        As[lk + 0][lm] = a4.x;
        As[lk + 1][lm] = a4.y;
        As[lk + 2][lm] = a4.z;
        As[lk + 3][lm] = a4.w;
        *(float4*)&Bs[wk][wn] = *(const float4*)(Wg + (size_t)k0 * HH);
        __syncthreads();

#pragma unroll
        for (int kk = 0; kk < 8; kk++) {
            float a[8], b[8];
            *(float4*)&a[0] = *(const float4*)&As[kk][tm];
            *(float4*)&a[4] = *(const float4*)&As[kk][tm + 4];
            *(float4*)&b[0] = *(const float4*)&Bs[kk][tn];
            *(float4*)&b[4] = *(const float4*)&Bs[kk][tn + 4];
#pragma unroll
            for (int i = 0; i < 8; i++)
#pragma unroll
                for (int j = 0; j < 8; j++)
                    acc[i][j] += a[i] * b[j];
        }
        __syncthreads();
    }

    // epilogue: sigmoid + bias
#pragma unroll
    for (int i = 0; i < 8; i++) {
        size_t m = (size_t)(bm + tm + i);
        float* zr = g_z + m * HH + bn + tn;
#pragma unroll
        for (int j = 0; j < 8; j++) {
            float v = acc[i][j] + bw[bn + tn + j];
            zr[j] = 1.0f / (1.0f + expf(-v));
        }
    }
}

// ---------------- Phase 2: persistent recurrent scan -------------------------
// 128 CTAs. CTA cid owns output columns h in [cid*4, cid*4+4), i.e. r-columns
// {h, h+512} (i and o gates) -> 8 R columns cached in smem for the whole scan.
// Within a CTA: warp = k-slice (kg = warp id, 64 k each, smem-broadcast R),
// lane = 2 consecutive batches. Partial sums reduced via smem each step.
__global__ __launch_bounds__(256) void scan_kernel(
    const float* __restrict__ Rm,   // [512][1024] row-major
    const float* __restrict__ br,   // [1024]
    const float* __restrict__ y0,   // [B][H]
    const float* __restrict__ c0,   // [B][H]
    float* __restrict__ out)        // [T*B*H] outputs, then y_f[B*H], c_f[B*H]
{
    __shared__ float Rs[512][8];        // [k][c]  16 KB (persistent across scan)
    __shared__ float ps[8][8][64];      // [kg][c][b] partials, 16 KB
    __shared__ float cs[4][64];         // c state  [h_local][b]
    __shared__ float brs[8];

    const int tid = threadIdx.x;
    const int cid = blockIdx.x;
    const int h_base = cid * 4;

    const int bg = tid & 31;            // lane: 2 batches
    const int kg = tid >> 5;            // warp id: k-slice
    const int b0 = bg * 2;
    const int k0 = kg * 64;

    const int hl = tid >> 6;            // 0..3  (finalize mapping)
    const int bb = tid & 63;            // 0..63

    // Cache this CTA's 8 R columns (one-time strided read; R never re-read).
    for (int idx = tid; idx < 512 * 8; idx += NTHR) {
        int k = idx >> 3, c = idx & 7;
        int col = (c < 4) ? (h_base + c) : (512 + h_base + (c - 4));
        Rs[k][c] = Rm[(size_t)k * 1024 + col];
    }
    if (tid < 8) {
        int col = (tid < 4) ? (h_base + tid) : (512 + h_base + (tid - 4));
        brs[tid] = br[col];
    }
    // c state (transpose [b][h] -> [h_local][b])
    cs[hl][bb] = c0[(size_t)bb * HH + h_base + hl];

    // init y buffer 0 from y0 (transpose [b][h] -> [h][b]), grid-strided
    for (int idx = cid * NTHR + tid; idx < HH * BB; idx += NCTA * NTHR) {
        int h = idx >> 6, b = idx & 63;
        g_y[0][idx] = y0[(size_t)b * HH + h];
    }
    grid_barrier(NCTA);

    float yn = 0.0f;

    for (int t = 0; t < TT; t++) {
        const float* __restrict__ ycur = g_y[t & 1];
        float* __restrict__ ynext = g_y[(t + 1) & 1];

        // prefetch z for this (b, t, h) before the FMA loop (hide DRAM latency)
        const float zv = g_z[((size_t)bb * TT + t) * HH + h_base + hl];

        float acc[8][2];
#pragma unroll
        for (int c = 0; c < 8; c++) { acc[c][0] = 0.0f; acc[c][1] = 0.0f; }

        const float* yp = ycur + k0 * 64 + b0;
#pragma unroll 8
        for (int k = 0; k < 64; k++) {
            const float2 yv = *(const float2*)(yp + (k << 6));
            const float4 r0 = *(const float4*)&Rs[k0 + k][0];
            const float4 r1 = *(const float4*)&Rs[k0 + k][4];
            acc[0][0] += r0.x * yv.x;  acc[0][1] += r0.x * yv.y;
            acc[1][0] += r0.y * yv.x;  acc[1][1] += r0.y * yv.y;
            acc[2][0] += r0.z * yv.x;  acc[2][1] += r0.z * yv.y;
            acc[3][0] += r0.w * yv.x;  acc[3][1] += r0.w * yv.y;
            acc[4][0] += r1.x * yv.x;  acc[4][1] += r1.x * yv.y;
            acc[5][0] += r1.y * yv.x;  acc[5][1] += r1.y * yv.y;
            acc[6][0] += r1.z * yv.x;  acc[6][1] += r1.z * yv.y;
            acc[7][0] += r1.w * yv.x;  acc[7][1] += r1.w * yv.y;
        }

#pragma unroll
        for (int c = 0; c < 8; c++)
            *(float2*)&ps[kg][c][b0] = make_float2(acc[c][0], acc[c][1]);
        __syncthreads();

        // reduce 8 k-slices, then gate math
        float ri = 0.0f, ro = 0.0f;
#pragma unroll
        for (int g = 0; g < 8; g++) {
            ri += ps[g][hl][bb];
            ro += ps[g][4 + hl][bb];
        }
        ri = tanhf(ri + brs[hl]);
        ro = tanhf(ro + brs[4 + hl]);
        float cc = cs[hl][bb] + ri * zv;
        cs[hl][bb] = cc;
        yn = ro * tanhf(cc);

        out[((size_t)t * BB + bb) * HH + h_base + hl] = yn;
        ynext[(h_base + hl) * 64 + bb] = yn;

        grid_barrier(NCTA);   // leading __syncthreads also protects ps reuse
    }

    // finals: y_f then c_f, each [B][H]
    const size_t base = (size_t)TT * BB * HH;
    out[base + (size_t)bb * HH + h_base + hl] = yn;
    out[base + (size_t)BB * HH + (size_t)bb * HH + h_base + hl] = cs[hl][bb];
}

// ---------------- launch ------------------------------------------------------
extern "C" void kernel_launch(void* const* d_in, const int* in_sizes, int n_in,
                              void* d_out, int out_size) {
    (void)in_sizes; (void)n_in; (void)out_size;
    const float* x  = (const float*)d_in[0];
    const float* W  = (const float*)d_in[1];
    const float* R  = (const float*)d_in[2];
    const float* br = (const float*)d_in[3];
    const float* bw = (const float*)d_in[4];
    const float* y0 = (const float*)d_in[5];
    const float* c0 = (const float*)d_in[6];
    float* out = (float*)d_out;

    dim3 g1(HH / 128, (BB * TT) / 128);
    zgemm_kernel<<<g1, 256>>>(x, W, bw);
    scan_kernel<<<NCTA, NTHR>>>(R, br, y0, c0, out);
}

// round 3
// speedup vs baseline: 1.0027x; 1.0027x over previous
#include <cuda_runtime.h>
#include <cstdint>
#include <math.h>

#define BB 64
#define TT 1024
#define II 512
#define HH 512

#define NCTA 128
#define NTHR 256

// ---------------- device scratch (static allocs are the sanctioned scratch) ---
__device__ float g_z[(size_t)BB * TT * HH];   // sigmoid(x@W + b_w), [(b*T+t)][h]
__device__ float g_y[2][HH * BB];             // recurrent state, [h][b] layout
__device__ unsigned int g_bar_count;
__device__ unsigned int g_bar_gen;

// ---------------- grid barrier (128 co-resident CTAs) ------------------------
__device__ __forceinline__ void grid_barrier(unsigned int nctas) {
    __syncthreads();
    __threadfence();
    if (threadIdx.x == 0) {
        unsigned int gen = *(volatile unsigned int*)&g_bar_gen;
        unsigned int ticket = atomicAdd(&g_bar_count, 1u);
        if (ticket == nctas - 1u) {
            atomicExch(&g_bar_count, 0u);
            __threadfence();
            atomicAdd(&g_bar_gen, 1u);
        } else {
            while (*(volatile unsigned int*)&g_bar_gen == gen) { }
        }
    }
    __syncthreads();
    __threadfence();
}

// ---------------- Phase 1: z = sigmoid(x @ W + b_w) --------------------------
// M = B*T = 65536, K = I = 512, N = H = 512
// BM=BN=128, BK=8, 256 threads, 8x8 register tile per thread.
__global__ __launch_bounds__(256) void zgemm_kernel(
    const float* __restrict__ x, const float* __restrict__ W,
    const float* __restrict__ bw)
{
    __shared__ float As[8][128];   // [k][m]
    __shared__ float Bs[8][128];   // [k][n]

    const int tid = threadIdx.x;
    const int bm = blockIdx.y * 128;
    const int bn = blockIdx.x * 128;

    const int lm = tid >> 1;            // 0..127
    const int lk = (tid & 1) * 4;       // 0 or 4
    const int wk = tid >> 5;            // 0..7
    const int wn = (tid & 31) * 4;      // 0..124

    const int tm = (tid >> 4) * 8;      // 0..120
    const int tn = (tid & 15) * 8;      // 0..120

    float acc[8][8];
#pragma unroll
    for (int i = 0; i < 8; i++)
#pragma unroll
        for (int j = 0; j < 8; j++) acc[i][j] = 0.0f;

    const float* xg = x + (size_t)(bm + lm) * II + lk;
    const float* Wg = W + (size_t)wk * HH + bn + wn;

    for (int k0 = 0; k0 < II; k0 += 8) {
        float4 a4 = *(const float4*)(xg + k0);
        As[lk + 0][lm] = a4.x;
        As[lk + 1][lm] = a4.y;
        As[lk + 2][lm] = a4.z;
        As[lk + 3][lm] = a4.w;
        *(float4*)&Bs[wk][wn] = *(const float4*)(Wg + (size_t)k0 * HH);
        __syncthreads();

#pragma unroll
        for (int kk = 0; kk < 8; kk++) {
            float a[8], b[8];
            *(float4*)&a[0] = *(const float4*)&As[kk][tm];
            *(float4*)&a[4] = *(const float4*)&As[kk][tm + 4];
            *(float4*)&b[0] = *(const float4*)&Bs[kk][tn];
            *(float4*)&b[4] = *(const float4*)&Bs[kk][tn + 4];
#pragma unroll
            for (int i = 0; i < 8; i++)
#pragma unroll
                for (int j = 0; j < 8; j++)
                    acc[i][j] += a[i] * b[j];
        }
        __syncthreads();
    }

    // epilogue: sigmoid + bias
#pragma unroll
    for (int i = 0; i < 8; i++) {
        size_t m = (size_t)(bm + tm + i);
        float* zr = g_z + m * HH + bn + tn;
#pragma unroll
        for (int j = 0; j < 8; j++) {
            float v = acc[i][j] + bw[bn + tn + j];
            zr[j] = 1.0f / (1.0f + expf(-v));
        }
    }
}

// ---------------- Phase 2: persistent recurrent scan -------------------------
// 128 CTAs. CTA cid owns output columns h in [cid*4, cid*4+4), i.e. r-columns
// {h, h+512} (i and o gates) -> 8 R columns cached in smem for the whole scan.
// Within a CTA: warp = k-slice (kg = warp id, 64 k each, smem-broadcast R),
// lane = 2 consecutive batches. Partial sums reduced via smem each step.
__global__ __launch_bounds__(256) void scan_kernel(
    const float* __restrict__ Rm,   // [512][1024] row-major
    const float* __restrict__ br,   // [1024]
    const float* __restrict__ y0,   // [B][H]
    const float* __restrict__ c0,   // [B][H]
    float* __restrict__ out)        // [T*B*H] outputs, then y_f[B*H], c_f[B*H]
{
    __shared__ float Rs[512][8];        // [k][c]  16 KB (persistent across scan)
    __shared__ float ps[8][8][64];      // [kg][c][b] partials, 16 KB
    __shared__ float cs[4][64];         // c state  [h_local][b]
    __shared__ float brs[8];

    const int tid = threadIdx.x;
    const int cid = blockIdx.x;
    const int h_base = cid * 4;

    const int bg = tid & 31;            // lane: 2 batches
    const int kg = tid >> 5;            // warp id: k-slice
    const int b0 = bg * 2;
    const int k0 = kg * 64;

    const int hl = tid >> 6;            // 0..3  (finalize mapping)
    const int bb = tid & 63;            // 0..63

    // Cache this CTA's 8 R columns (one-time strided read; R never re-read).
    for (int idx = tid; idx < 512 * 8; idx += NTHR) {
        int k = idx >> 3, c = idx & 7;
        int col = (c < 4) ? (h_base + c) : (512 + h_base + (c - 4));
        Rs[k][c] = Rm[(size_t)k * 1024 + col];
    }
    if (tid < 8) {
        int col = (tid < 4) ? (h_base + tid) : (512 + h_base + (tid - 4));
        brs[tid] = br[col];
    }
    // c state (transpose [b][h] -> [h_local][b])
    cs[hl][bb] = c0[(size_t)bb * HH + h_base + hl];

    // init y buffer 0 from y0 (transpose [b][h] -> [h][b]), grid-strided
    for (int idx = cid * NTHR + tid; idx < HH * BB; idx += NCTA * NTHR) {
        int h = idx >> 6, b = idx & 63;
        g_y[0][idx] = y0[(size_t)b * HH + h];
    }
    grid_barrier(NCTA);

    float yn = 0.0f;

    for (int t = 0; t < TT; t++) {
        const float* __restrict__ ycur = g_y[t & 1];
        float* __restrict__ ynext = g_y[(t + 1) & 1];

        // prefetch z for this (b, t, h) before the FMA loop (hide DRAM latency)
        const float zv = g_z[((size_t)bb * TT + t) * HH + h_base + hl];

        float acc[8][2];
#pragma unroll
        for (int c = 0; c < 8; c++) { acc[c][0] = 0.0f; acc[c][1] = 0.0f; }

        const float* yp = ycur + k0 * 64 + b0;
#pragma unroll 8
        for (int k = 0; k < 64; k++) {
            const float2 yv = *(const float2*)(yp + (k << 6));
            const float4 r0 = *(const float4*)&Rs[k0 + k][0];
            const float4 r1 = *(const float4*)&Rs[k0 + k][4];
            acc[0][0] += r0.x * yv.x;  acc[0][1] += r0.x * yv.y;
            acc[1][0] += r0.y * yv.x;  acc[1][1] += r0.y * yv.y;
            acc[2][0] += r0.z * yv.x;  acc[2][1] += r0.z * yv.y;
            acc[3][0] += r0.w * yv.x;  acc[3][1] += r0.w * yv.y;
            acc[4][0] += r1.x * yv.x;  acc[4][1] += r1.x * yv.y;
            acc[5][0] += r1.y * yv.x;  acc[5][1] += r1.y * yv.y;
            acc[6][0] += r1.z * yv.x;  acc[6][1] += r1.z * yv.y;
            acc[7][0] += r1.w * yv.x;  acc[7][1] += r1.w * yv.y;
        }

#pragma unroll
        for (int c = 0; c < 8; c++)
            *(float2*)&ps[kg][c][b0] = make_float2(acc[c][0], acc[c][1]);
        __syncthreads();

        // reduce 8 k-slices, then gate math
        float ri = 0.0f, ro = 0.0f;
#pragma unroll
        for (int g = 0; g < 8; g++) {
            ri += ps[g][hl][bb];
            ro += ps[g][4 + hl][bb];
        }
        ri = tanhf(ri + brs[hl]);
        ro = tanhf(ro + brs[4 + hl]);
        float cc = cs[hl][bb] + ri * zv;
        cs[hl][bb] = cc;
        yn = ro * tanhf(cc);

        out[((size_t)t * BB + bb) * HH + h_base + hl] = yn;
        ynext[(h_base + hl) * 64 + bb] = yn;

        grid_barrier(NCTA);   // leading __syncthreads also protects ps reuse
    }

    // finals: y_f then c_f, each [B][H]
    const size_t base = (size_t)TT * BB * HH;
    out[base + (size_t)bb * HH + h_base + hl] = yn;
    out[base + (size_t)BB * HH + (size_t)bb * HH + h_base + hl] = cs[hl][bb];
}

// ---------------- launch ------------------------------------------------------
extern "C" void kernel_launch(void* const* d_in, const int* in_sizes, int n_in,
                              void* d_out, int out_size) {
    (void)in_sizes; (void)n_in; (void)out_size;
    const float* x  = (const float*)d_in[0];
    const float* W  = (const float*)d_in[1];
    const float* R  = (const float*)d_in[2];
    const float* br = (const float*)d_in[3];
    const float* bw = (const float*)d_in[4];
    const float* y0 = (const float*)d_in[5];
    const float* c0 = (const float*)d_in[6];
    float* out = (float*)d_out;

    dim3 g1(HH / 128, (BB * TT) / 128);
    zgemm_kernel<<<g1, 256>>>(x, W, bw);
    scan_kernel<<<NCTA, NTHR>>>(R, br, y0, c0, out);
}